// round 3
// baseline (speedup 1.0000x reference)
#include <cuda_runtime.h>
#include <stdint.h>

#define NB 8
#define NC 80
#define NA 3
#define NHW 5776
#define NN (NA * NHW)        /* 17328 */
#define NBC (NB * NC)        /* 640 */
#define TOPK 200
#define CAP 1024
#define NBINS 4096
#define NW 7                 /* ceil(200/32) */
#define HI_BITS 0x3F7AE000u  /* v >= 0.9799805f */

// Static device scratch (no allocs): per-(b,c) candidate lists + counts.
__device__ unsigned long long g_cand[(size_t)NBC * CAP];  // 5.24 MB
__device__ int g_cnt[NBC];

// ---------------------------------------------------------------------------
__global__ void zero_k() {
    int i = blockIdx.x * blockDim.x + threadIdx.x;
    if (i < NBC) g_cnt[i] = 0;
}

// ---------------------------------------------------------------------------
// Collect: one coalesced float4 pass over scores (B, N, C). A float4 covers
// 4 consecutive classes of the same (b, n). Push high-score items to the
// per-(b,c) list; count is exact even past CAP.
// ---------------------------------------------------------------------------
__global__ __launch_bounds__(256) void collect_k(const float* __restrict__ scores) {
    const int f = blockIdx.x * 256 + threadIdx.x;          // float4 index
    float4 v4 = reinterpret_cast<const float4*>(scores)[f];
    const int e  = f * 4;                                  // element index
    const int b  = e / (NN * NC);
    const int r  = e - b * (NN * NC);
    const int n  = r / NC;
    const int c0 = r - n * NC;

    float vv[4] = {v4.x, v4.y, v4.z, v4.w};
    #pragma unroll
    for (int u = 0; u < 4; u++) {
        uint32_t bits = __float_as_uint(vv[u]);
        if (bits >= HI_BITS) {
            int bc = b * NC + c0 + u;
            int p = atomicAdd(&g_cnt[bc], 1);
            if (p < CAP)
                g_cand[(size_t)bc * CAP + p] =
                    ((unsigned long long)bits << 32) | (~(uint32_t)n);
        }
    }
}

// ---------------------------------------------------------------------------
// NMS: one CTA per (b, c).
// ---------------------------------------------------------------------------
__device__ __forceinline__ uint32_t score_bin(uint32_t bits) {
    return (bits >= 0x3F800000u) ? (NBINS - 1) : ((bits - 0x3F000000u) >> 11);
}

__global__ __launch_bounds__(256) void nms_k(const float* __restrict__ boxes,
                                             const float* __restrict__ scores,
                                             float* __restrict__ out) {
    const int bc  = blockIdx.x;
    const int b   = bc / NC;
    const int c   = bc % NC;
    const int tid = threadIdx.x;

    __shared__ unsigned long long cand[CAP];
    __shared__ uint32_t hist[NBINS];       // fallback only
    __shared__ uint32_t part[256];
    __shared__ uint32_t candCnt;
    __shared__ int cutBin;
    __shared__ float4 sbox[TOPK];
    __shared__ float sar[TOPK], ssc[TOPK];
    __shared__ uint32_t smat[TOPK * NW];
    __shared__ uint32_t skeepw[NW];

    const int cnt = g_cnt[bc];
    int cc;

    if (cnt >= TOPK && cnt <= CAP) {
        // ---- main path: candidates already collected ----
        const unsigned long long* src = &g_cand[(size_t)bc * CAP];
        for (int i = tid; i < cnt; i += 256) cand[i] = src[i];
        cc = cnt;
        __syncthreads();
    } else {
        // ---- fallback (exactness guard, ~never taken): strided histogram ----
        for (int i = tid; i < NBINS; i += 256) hist[i] = 0u;
        if (tid == 0) candCnt = 0u;
        __syncthreads();
        const float* base = scores + (size_t)b * NN * NC + c;
        for (int i = tid; i < NN; i += 256) {
            float v = base[(size_t)i * NC];
            if (v > 0.5f) atomicAdd(&hist[score_bin(__float_as_uint(v))], 1u);
        }
        __syncthreads();
        uint32_t ps = 0;
        #pragma unroll
        for (int k = 0; k < 16; k++) ps += hist[tid * 16 + k];
        part[tid] = ps;
        __syncthreads();
        if (tid == 0) {
            uint32_t suf = 0; int g = -1; uint32_t sufG = 0;
            for (int t = 255; t >= 0; t--) {
                uint32_t ns = suf + part[t];
                if (ns >= TOPK) { g = t; sufG = suf; break; }
                suf = ns;
            }
            int hstar = 0;
            if (g >= 0) {
                uint32_t run = sufG;
                for (int bn = g * 16 + 15; bn >= g * 16; bn--) {
                    run += hist[bn];
                    if (run >= TOPK) { hstar = bn; break; }
                }
            }
            cutBin = hstar;
        }
        __syncthreads();
        const int hstar = cutBin;
        for (int i = tid; i < NN; i += 256) {
            float v = base[(size_t)i * NC];
            if (v > 0.5f) {
                uint32_t bits = __float_as_uint(v);
                if (score_bin(bits) >= (uint32_t)hstar) {
                    uint32_t p = atomicAdd(&candCnt, 1u);
                    if (p < CAP)
                        cand[p] = ((unsigned long long)bits << 32) | (~(uint32_t)i);
                }
            }
        }
        __syncthreads();
        cc = (candCnt < (uint32_t)CAP) ? (int)candCnt : CAP;
    }

    // ---- pad + bitonic sort (descending), direct pair indexing ----
    const int M = (cc <= 256) ? 256 : (cc <= 512 ? 512 : CAP);
    for (int i = tid; i < M; i += 256)
        if (i >= cc) cand[i] = 0ULL;
    __syncthreads();

    for (int k = 2; k <= M; k <<= 1) {
        for (int j = k >> 1; j > 0; j >>= 1) {
            for (int p = tid; p < (M >> 1); p += 256) {
                int i   = ((p & ~(j - 1)) << 1) | (p & (j - 1));
                int ixj = i | j;
                unsigned long long a = cand[i], bb = cand[ixj];
                bool desc = ((i & k) == 0);
                if (desc ? (a < bb) : (a > bb)) { cand[i] = bb; cand[ixj] = a; }
            }
            __syncthreads();
        }
    }

    const int nTop = (cc < TOPK) ? cc : TOPK;

    // ---- gather winner boxes ----
    if (tid < TOPK) {
        if (tid < nTop) {
            unsigned long long key = cand[tid];
            uint32_t idx = ~(uint32_t)(key & 0xFFFFFFFFull);
            float sc = __uint_as_float((uint32_t)(key >> 32));
            float4 bx = reinterpret_cast<const float4*>(boxes)[(size_t)b * NN + idx];
            sbox[tid] = bx;
            sar[tid]  = (bx.z - bx.x) * (bx.w - bx.y);
            ssc[tid]  = sc;
        } else {
            sbox[tid] = make_float4(0.f, 0.f, 0.f, 0.f);
            sar[tid]  = 0.f; ssc[tid] = 0.f;
        }
    }
    __syncthreads();

    // ---- suppression matrix, division-free fast path ----
    for (int idx = tid; idx < TOPK * NW; idx += 256) {
        int i = idx / NW, w = idx % NW;
        uint32_t m = 0u;
        if (i < nTop) {
            float4 bi = sbox[i];
            float  ai = sar[i];
            int j0 = w * 32;
            int jend = j0 + 32; if (jend > nTop) jend = nTop;
            int jbeg = (i + 1 > j0) ? (i + 1) : j0;
            for (int j = jbeg; j < jend; j++) {
                float4 bj = sbox[j];
                float xx1 = fmaxf(bi.x, bj.x), yy1 = fmaxf(bi.y, bj.y);
                float xx2 = fminf(bi.z, bj.z), yy2 = fminf(bi.w, bj.w);
                float inter = fmaxf(0.f, xx2 - xx1) * fmaxf(0.f, yy2 - yy1);
                float denom = ai + sar[j] - inter;
                float t2 = inter + inter;
                bool sup;
                if (t2 > denom * 1.00002f)      sup = true;
                else if (t2 < denom * 0.99998f) sup = false;
                else                            sup = (inter / denom > 0.5f);
                if (sup) m |= (1u << (j - j0));
            }
        }
        smat[i * NW + w] = m;
    }
    __syncthreads();

    // ---- greedy scan with row prefetch (exact reference semantics) ----
    if (tid == 0) {
        uint32_t rm[NW], row[NW], nxt[NW];
        #pragma unroll
        for (int w = 0; w < NW; w++) { rm[w] = 0u; row[w] = smat[w]; }
        for (int i = 0; i < nTop; i++) {
            if (i + 1 < nTop) {
                #pragma unroll
                for (int w = 0; w < NW; w++) nxt[w] = smat[(i + 1) * NW + w];
            }
            if (!((rm[i >> 5] >> (i & 31)) & 1u)) {
                #pragma unroll
                for (int w = 0; w < NW; w++) rm[w] |= row[w];
            }
            #pragma unroll
            for (int w = 0; w < NW; w++) row[w] = nxt[w];
        }
        #pragma unroll
        for (int w = 0; w < NW; w++) skeepw[w] = ~rm[w];
    }
    __syncthreads();

    // ---- output (B, C, TOPK, 6) ----
    if (tid < TOPK) {
        bool kp = (tid < nTop) && ((skeepw[tid >> 5] >> (tid & 31)) & 1u);
        size_t o = ((size_t)bc * TOPK + tid) * 6;
        float4 bx = sbox[tid];
        out[o + 0] = kp ? bx.x : 0.f;
        out[o + 1] = kp ? bx.y : 0.f;
        out[o + 2] = kp ? bx.z : 0.f;
        out[o + 3] = kp ? bx.w : 0.f;
        out[o + 4] = kp ? ssc[tid] : 0.f;
        out[o + 5] = kp ? (float)c : 0.f;
    }
}

// ---------------------------------------------------------------------------
extern "C" void kernel_launch(void* const* d_in, const int* in_sizes, int n_in,
                              void* d_out, int out_size) {
    const float* boxes  = (const float*)d_in[0];   // (8, 3, 5776, 4)
    const float* scores = (const float*)d_in[1];   // (8, 3, 5776, 80)
    float* out = (float*)d_out;                    // (8, 80, 200, 6)

    zero_k<<<3, 256>>>();
    collect_k<<<(NB * NN * NC) / (4 * 256), 256>>>(scores);   // 10830 CTAs
    nms_k<<<NBC, 256>>>(boxes, scores, out);
}

// round 4
// speedup vs baseline: 1.3949x; 1.3949x over previous
#include <cuda_runtime.h>
#include <stdint.h>

#define NB 8
#define NC 80
#define NA 3
#define NHW 5776
#define NN (NA * NHW)        /* 17328 */
#define NBC (NB * NC)        /* 640 */
#define TOPK 200
#define CAP 1024
#define NBINS 4096
#define NW 7                 /* ceil(200/32) */
#define HI_BITS 0x3F7AE000u  /* v >= 0.9799805f */

// 44.3 MB scratch for transposed scores [B][C][N]
__device__ float g_scoresT[(size_t)NB * NC * NN];

// ---------------------------------------------------------------------------
// Kernel 1: transpose scores (B, N, C) -> (B, C, N), float4 gmem I/O.
// ---------------------------------------------------------------------------
__global__ __launch_bounds__(256) void transpose_k(const float* __restrict__ scores) {
    __shared__ float tile[48 * 81];   // pad 80->81
    const int b  = blockIdx.y;
    const int n0 = blockIdx.x * 48;
    const float4* src4 = reinterpret_cast<const float4*>(
        scores + ((size_t)b * NN + n0) * NC);

    for (int f = threadIdx.x; f < 48 * 20; f += 256) {
        float4 v = src4[f];
        int r = f / 20, c4 = f % 20;
        float* p = &tile[r * 81 + c4 * 4];
        p[0] = v.x; p[1] = v.y; p[2] = v.z; p[3] = v.w;
    }
    __syncthreads();

    for (int f = threadIdx.x; f < NC * 12; f += 256) {
        int c = f / 12, rq = f % 12;
        float4 v = make_float4(tile[(rq * 4 + 0) * 81 + c],
                               tile[(rq * 4 + 1) * 81 + c],
                               tile[(rq * 4 + 2) * 81 + c],
                               tile[(rq * 4 + 3) * 81 + c]);
        *reinterpret_cast<float4*>(
            &g_scoresT[((size_t)b * NC + c) * NN + n0 + rq * 4]) = v;
    }
}

// ---------------------------------------------------------------------------
// Kernel 2: one CTA per (b, c). Shared-memory threshold stash (no histogram
// on the hot path, no global atomics), bitonic sort, bitmask NMS.
// ---------------------------------------------------------------------------
__device__ __forceinline__ uint32_t score_bin(uint32_t bits) {
    return (bits >= 0x3F800000u) ? (NBINS - 1) : ((bits - 0x3F000000u) >> 11);
}

__global__ __launch_bounds__(256) void nms_k(const float* __restrict__ boxes,
                                             float* __restrict__ out) {
    const int bc  = blockIdx.x;
    const int b   = bc / NC;
    const int c   = bc % NC;
    const int tid = threadIdx.x;
    const float* base = g_scoresT + (size_t)bc * NN;

    __shared__ unsigned long long cand[CAP];
    __shared__ uint32_t hist[NBINS];       // fallback only
    __shared__ uint32_t part[256];
    __shared__ uint32_t candCnt;
    __shared__ int cutBin;
    __shared__ float4 sbox[TOPK];
    __shared__ float sar[TOPK], ssc[TOPK];
    __shared__ uint32_t smat[TOPK * NW];
    __shared__ uint32_t skeepw[NW];

    if (tid == 0) candCnt = 0u;
    __syncthreads();

    // ---- Pass 1: coalesced float4 scan, stash items >= 0.98 (shared atomics,
    //      ~346 expected per CTA) ----
    const float4* base4 = reinterpret_cast<const float4*>(base);
    for (int k = tid; k < NN / 4; k += 256) {
        float4 v4 = base4[k];
        uint32_t bb[4] = {__float_as_uint(v4.x), __float_as_uint(v4.y),
                          __float_as_uint(v4.z), __float_as_uint(v4.w)};
        #pragma unroll
        for (int u = 0; u < 4; u++) {
            if (bb[u] >= HI_BITS) {
                uint32_t p = atomicAdd(&candCnt, 1u);
                if (p < CAP) {
                    uint32_t i = (uint32_t)(4 * k + u);
                    cand[p] = ((unsigned long long)bb[u] << 32) | (~i);
                }
            }
        }
    }
    __syncthreads();

    int cc;
    uint32_t cnt = candCnt;

    if (cnt >= TOPK && cnt <= CAP) {
        cc = (int)cnt;                        // fast path: stash is exact superset
    } else {
        // ---- fallback (exactness guard, ~never taken on this data) ----
        for (int i = tid; i < NBINS; i += 256) hist[i] = 0u;
        if (tid == 0) candCnt = 0u;
        __syncthreads();
        for (int i = tid; i < NN; i += 256) {
            float v = base[i];
            if (v > 0.5f) atomicAdd(&hist[score_bin(__float_as_uint(v))], 1u);
        }
        __syncthreads();
        uint32_t ps = 0;
        #pragma unroll
        for (int k = 0; k < 16; k++) ps += hist[tid * 16 + k];
        part[tid] = ps;
        __syncthreads();
        if (tid == 0) {
            uint32_t suf = 0; int g = -1; uint32_t sufG = 0;
            for (int t = 255; t >= 0; t--) {
                uint32_t ns = suf + part[t];
                if (ns >= TOPK) { g = t; sufG = suf; break; }
                suf = ns;
            }
            int hstar = 0;
            if (g >= 0) {
                uint32_t run = sufG;
                for (int bn = g * 16 + 15; bn >= g * 16; bn--) {
                    run += hist[bn];
                    if (run >= TOPK) { hstar = bn; break; }
                }
            }
            cutBin = hstar;
        }
        __syncthreads();
        const int hstar = cutBin;
        for (int i = tid; i < NN; i += 256) {
            float v = base[i];
            if (v > 0.5f) {
                uint32_t bits = __float_as_uint(v);
                if (score_bin(bits) >= (uint32_t)hstar) {
                    uint32_t p = atomicAdd(&candCnt, 1u);
                    if (p < CAP)
                        cand[p] = ((unsigned long long)bits << 32) | (~(uint32_t)i);
                }
            }
        }
        __syncthreads();
        cc = (candCnt < (uint32_t)CAP) ? (int)candCnt : CAP;
    }

    // ---- pad + bitonic sort (descending), direct pair indexing ----
    const int M = (cc <= 256) ? 256 : (cc <= 512 ? 512 : CAP);
    for (int i = tid; i < M; i += 256)
        if (i >= cc) cand[i] = 0ULL;
    __syncthreads();

    for (int k = 2; k <= M; k <<= 1) {
        for (int j = k >> 1; j > 0; j >>= 1) {
            for (int p = tid; p < (M >> 1); p += 256) {
                int i   = ((p & ~(j - 1)) << 1) | (p & (j - 1));
                int ixj = i | j;
                unsigned long long a = cand[i], bb = cand[ixj];
                bool desc = ((i & k) == 0);
                if (desc ? (a < bb) : (a > bb)) { cand[i] = bb; cand[ixj] = a; }
            }
            __syncthreads();
        }
    }

    const int nTop = (cc < TOPK) ? cc : TOPK;

    // ---- gather winner boxes ----
    if (tid < TOPK) {
        if (tid < nTop) {
            unsigned long long key = cand[tid];
            uint32_t idx = ~(uint32_t)(key & 0xFFFFFFFFull);
            float sc = __uint_as_float((uint32_t)(key >> 32));
            float4 bx = reinterpret_cast<const float4*>(boxes)[(size_t)b * NN + idx];
            sbox[tid] = bx;
            sar[tid]  = (bx.z - bx.x) * (bx.w - bx.y);
            ssc[tid]  = sc;
        } else {
            sbox[tid] = make_float4(0.f, 0.f, 0.f, 0.f);
            sar[tid]  = 0.f; ssc[tid] = 0.f;
        }
    }
    __syncthreads();

    // ---- suppression matrix (division-free fast path) ----
    for (int idx = tid; idx < TOPK * NW; idx += 256) {
        int i = idx / NW, w = idx % NW;
        uint32_t m = 0u;
        if (i < nTop) {
            float4 bi = sbox[i];
            float  ai = sar[i];
            int j0 = w * 32;
            int jend = j0 + 32; if (jend > nTop) jend = nTop;
            int jbeg = (i + 1 > j0) ? (i + 1) : j0;
            for (int j = jbeg; j < jend; j++) {
                float4 bj = sbox[j];
                float xx1 = fmaxf(bi.x, bj.x), yy1 = fmaxf(bi.y, bj.y);
                float xx2 = fminf(bi.z, bj.z), yy2 = fminf(bi.w, bj.w);
                float inter = fmaxf(0.f, xx2 - xx1) * fmaxf(0.f, yy2 - yy1);
                float denom = ai + sar[j] - inter;
                float t2 = inter + inter;
                bool sup;
                if (t2 > denom * 1.00002f)      sup = true;
                else if (t2 < denom * 0.99998f) sup = false;
                else                            sup = (inter / denom > 0.5f);
                if (sup) m |= (1u << (j - j0));
            }
        }
        smat[i * NW + w] = m;
    }
    __syncthreads();

    // ---- greedy scan with row prefetch (exact reference semantics) ----
    if (tid == 0) {
        uint32_t rm[NW], row[NW], nxt[NW];
        #pragma unroll
        for (int w = 0; w < NW; w++) { rm[w] = 0u; row[w] = smat[w]; }
        for (int i = 0; i < nTop; i++) {
            if (i + 1 < nTop) {
                #pragma unroll
                for (int w = 0; w < NW; w++) nxt[w] = smat[(i + 1) * NW + w];
            }
            if (!((rm[i >> 5] >> (i & 31)) & 1u)) {
                #pragma unroll
                for (int w = 0; w < NW; w++) rm[w] |= row[w];
            }
            #pragma unroll
            for (int w = 0; w < NW; w++) row[w] = nxt[w];
        }
        #pragma unroll
        for (int w = 0; w < NW; w++) skeepw[w] = ~rm[w];
    }
    __syncthreads();

    // ---- output (B, C, TOPK, 6) ----
    if (tid < TOPK) {
        bool kp = (tid < nTop) && ((skeepw[tid >> 5] >> (tid & 31)) & 1u);
        size_t o = ((size_t)bc * TOPK + tid) * 6;
        float4 bx = sbox[tid];
        out[o + 0] = kp ? bx.x : 0.f;
        out[o + 1] = kp ? bx.y : 0.f;
        out[o + 2] = kp ? bx.z : 0.f;
        out[o + 3] = kp ? bx.w : 0.f;
        out[o + 4] = kp ? ssc[tid] : 0.f;
        out[o + 5] = kp ? (float)c : 0.f;
    }
}

// ---------------------------------------------------------------------------
extern "C" void kernel_launch(void* const* d_in, const int* in_sizes, int n_in,
                              void* d_out, int out_size) {
    const float* boxes  = (const float*)d_in[0];   // (8, 3, 5776, 4)
    const float* scores = (const float*)d_in[1];   // (8, 3, 5776, 80)
    float* out = (float*)d_out;                    // (8, 80, 200, 6)

    dim3 g1(NN / 48, NB);
    transpose_k<<<g1, 256>>>(scores);
    nms_k<<<NBC, 256>>>(boxes, out);
}

// round 6
// speedup vs baseline: 1.5843x; 1.1358x over previous
#include <cuda_runtime.h>
#include <stdint.h>

#define NB 8
#define NC 80
#define NN 17328             /* 3*5776 */
#define NBC (NB * NC)        /* 640 */
#define TOPK 200
#define CAP 1024
#define NBINS 4096
#define NW 7                 /* ceil(200/32) */
#define HI_BITS 0x3F7AE000u  /* v >= 0.9799805f */
#define FULLM 0xFFFFFFFFu

// Static device scratch
__device__ float g_scoresT[(size_t)NB * NC * NN];        // 44.3 MB
__device__ float g_top[(size_t)NBC * TOPK * 6];          // x1,y1,x2,y2,score,area
__device__ int   g_ntop[NBC];

// ---------------------------------------------------------------------------
// Kernel 1: transpose scores (B, N, C) -> (B, C, N)
// ---------------------------------------------------------------------------
__global__ __launch_bounds__(256) void transpose_k(const float* __restrict__ scores) {
    __shared__ float tile[48 * 81];
    const int b  = blockIdx.y;
    const int n0 = blockIdx.x * 48;
    const float4* src4 = reinterpret_cast<const float4*>(
        scores + ((size_t)b * NN + n0) * NC);

    for (int f = threadIdx.x; f < 48 * 20; f += 256) {
        float4 v = src4[f];
        int r = f / 20, c4 = f % 20;
        float* p = &tile[r * 81 + c4 * 4];
        p[0] = v.x; p[1] = v.y; p[2] = v.z; p[3] = v.w;
    }
    __syncthreads();

    for (int f = threadIdx.x; f < NC * 12; f += 256) {
        int c = f / 12, rq = f % 12;
        float4 v = make_float4(tile[(rq * 4 + 0) * 81 + c],
                               tile[(rq * 4 + 1) * 81 + c],
                               tile[(rq * 4 + 2) * 81 + c],
                               tile[(rq * 4 + 3) * 81 + c]);
        *reinterpret_cast<float4*>(
            &g_scoresT[((size_t)b * NC + c) * NN + n0 + rq * 4]) = v;
    }
}

// ---------------------------------------------------------------------------
// Kernel 2: select_k — one CTA per (b,c): atomic-free streaming scan with
// warp-aggregated stash, 64-bit key bitonic sort, gather top-200 -> g_top.
// Key = (score_bits << 32) | ~n  => desc sort = (score desc, index asc).
// ---------------------------------------------------------------------------
__device__ __forceinline__ uint32_t score_bin(uint32_t bits) {
    return (bits >= 0x3F800000u) ? (NBINS - 1) : ((bits - 0x3F000000u) >> 11);
}

__global__ __launch_bounds__(256) void select_k(const float* __restrict__ boxes) {
    const int bc  = blockIdx.x;
    const int b   = bc / NC;
    const int tid = threadIdx.x;
    const int lane = tid & 31;
    const float* base = g_scoresT + (size_t)bc * NN;

    __shared__ unsigned long long cand[CAP];         // 8 KB
    __shared__ uint32_t hist[NBINS];                 // 16 KB (fallback only)
    __shared__ uint32_t part[256];
    __shared__ uint32_t candCnt;
    __shared__ int cutBin;

    if (tid == 0) candCnt = 0u;
    __syncthreads();

    // ---- streaming scan: per-thread stash, one shared atomic per warp ----
    unsigned long long mykeys[16];
    int h = 0;
    const float4* base4 = reinterpret_cast<const float4*>(base);
    for (int k = tid; k < NN / 4; k += 256) {
        float4 v4 = base4[k];
        uint32_t bb[4] = {__float_as_uint(v4.x), __float_as_uint(v4.y),
                          __float_as_uint(v4.z), __float_as_uint(v4.w)};
        #pragma unroll
        for (int uu = 0; uu < 4; uu++) {
            if (bb[uu] >= HI_BITS) {
                uint32_t n = (uint32_t)(4 * k + uu);
                if (h < 16)
                    mykeys[h] = ((unsigned long long)bb[uu] << 32) | (~n);
                h++;
            }
        }
    }

    // warp-aggregated reservation
    int inc = h;
    #pragma unroll
    for (int o = 1; o < 32; o <<= 1) {
        int v = __shfl_up_sync(FULLM, inc, o);
        if (lane >= o) inc += v;
    }
    int exc = inc - h;
    int tot = __shfl_sync(FULLM, inc, 31);
    uint32_t wbase = 0;
    if (lane == 0) wbase = atomicAdd(&candCnt, (uint32_t)tot);
    wbase = __shfl_sync(FULLM, wbase, 0);
    int hw = (h < 16) ? h : 16;
    for (int t = 0; t < hw; t++) {
        uint32_t p = wbase + (uint32_t)exc + (uint32_t)t;
        if (p < CAP) cand[p] = mykeys[t];
    }
    __syncthreads();

    uint32_t cnt = candCnt;
    bool fast = (cnt >= TOPK) && (cnt <= CAP) && (h <= 16);
    // h<=16 is per-thread; reduce: any overflow forces fallback
    fast = __syncthreads_and(fast);
    int cc;

    if (fast) {
        cc = (int)cnt;
    } else {
        // ---- exactness fallback (cold): histogram cut + rescan ----
        for (int i = tid; i < NBINS; i += 256) hist[i] = 0u;
        if (tid == 0) candCnt = 0u;
        __syncthreads();
        for (int i = tid; i < NN; i += 256) {
            float v = base[i];
            if (v > 0.5f) atomicAdd(&hist[score_bin(__float_as_uint(v))], 1u);
        }
        __syncthreads();
        uint32_t ps = 0;
        #pragma unroll
        for (int k = 0; k < 16; k++) ps += hist[tid * 16 + k];
        part[tid] = ps;
        __syncthreads();
        if (tid == 0) {
            uint32_t suf = 0; int g = -1; uint32_t sufG = 0;
            for (int t = 255; t >= 0; t--) {
                uint32_t ns = suf + part[t];
                if (ns >= TOPK) { g = t; sufG = suf; break; }
                suf = ns;
            }
            int hstar = 0;
            if (g >= 0) {
                uint32_t run = sufG;
                for (int bn = g * 16 + 15; bn >= g * 16; bn--) {
                    run += hist[bn];
                    if (run >= TOPK) { hstar = bn; break; }
                }
            }
            cutBin = hstar;
        }
        __syncthreads();
        const int hstar = cutBin;
        for (int i = tid; i < NN; i += 256) {
            float v = base[i];
            if (v > 0.5f) {
                uint32_t bits = __float_as_uint(v);
                if (score_bin(bits) >= (uint32_t)hstar) {
                    uint32_t p = atomicAdd(&candCnt, 1u);
                    if (p < CAP)
                        cand[p] = ((unsigned long long)bits << 32) | (~(uint32_t)i);
                }
            }
        }
        __syncthreads();
        cc = (candCnt < (uint32_t)CAP) ? (int)candCnt : CAP;
    }

    // ---- pad + bitonic sort (descending), direct pair indexing ----
    const int M = (cc <= 256) ? 256 : (cc <= 512 ? 512 : CAP);
    for (int i = tid; i < M; i += 256)
        if (i >= cc) cand[i] = 0ULL;
    __syncthreads();

    for (int k = 2; k <= M; k <<= 1) {
        for (int j = k >> 1; j > 0; j >>= 1) {
            for (int p = tid; p < (M >> 1); p += 256) {
                int i   = ((p & ~(j - 1)) << 1) | (p & (j - 1));
                int ixj = i | j;
                unsigned long long a = cand[i], bb = cand[ixj];
                bool desc = ((i & k) == 0);
                if (desc ? (a < bb) : (a > bb)) { cand[i] = bb; cand[ixj] = a; }
            }
            __syncthreads();
        }
    }

    const int nTop = (cc < TOPK) ? cc : TOPK;
    if (tid == 0) g_ntop[bc] = nTop;

    // ---- gather winners -> g_top[bc][t][6] ----
    if (tid < TOPK) {
        float x1 = 0.f, y1 = 0.f, x2 = 0.f, y2 = 0.f, sc = 0.f, ar = 0.f;
        if (tid < nTop) {
            unsigned long long key = cand[tid];
            uint32_t idx  = ~(uint32_t)(key & 0xFFFFFFFFull);
            uint32_t bits = (uint32_t)(key >> 32);
            float4 bx = reinterpret_cast<const float4*>(boxes)[(size_t)b * NN + idx];
            x1 = bx.x; y1 = bx.y; x2 = bx.z; y2 = bx.w;
            sc = __uint_as_float(bits);
            ar = (x2 - x1) * (y2 - y1);
        }
        float* dst = &g_top[((size_t)bc * TOPK + tid) * 6];
        dst[0] = x1; dst[1] = y1; dst[2] = x2; dst[3] = y2;
        dst[4] = sc; dst[5] = ar;
    }
}

// ---------------------------------------------------------------------------
// Kernel 3: nmsfin_k — ballot suppression matrix, greedy scan, masked output.
// ---------------------------------------------------------------------------
__global__ __launch_bounds__(256) void nmsfin_k(float* __restrict__ out) {
    const int bc  = blockIdx.x;
    const int c   = bc % NC;
    const int tid = threadIdx.x;

    __shared__ float4 sbox[TOPK];
    __shared__ float  sar[TOPK], ssc[TOPK];
    __shared__ uint32_t smat[TOPK * NW];
    __shared__ uint32_t skeepw[NW];

    const int nTop = g_ntop[bc];

    const float* src = &g_top[(size_t)bc * TOPK * 6];
    for (int e = tid; e < TOPK * 6; e += 256) {
        int t = e / 6, q = e % 6;
        float v = src[e];
        if      (q == 0) sbox[t].x = v;
        else if (q == 1) sbox[t].y = v;
        else if (q == 2) sbox[t].z = v;
        else if (q == 3) sbox[t].w = v;
        else if (q == 4) ssc[t] = v;
        else             sar[t] = v;
    }
    __syncthreads();

    // ---- suppression matrix via ballot: warp w owns columns [32w, 32w+32) ----
    if (tid < NW * 32) {
        const int w = tid >> 5;
        const int j = tid;
        float4 bj = make_float4(0.f, 0.f, 0.f, 0.f);
        float  aj = 0.f;
        bool valid = (j < nTop);
        if (valid) { bj = sbox[j]; aj = sar[j]; }
        for (int i = 0; i < nTop; i++) {
            float4 bi = sbox[i];
            float  ai = sar[i];
            bool sup = false;
            if (valid && j > i) {
                float xx1 = fmaxf(bi.x, bj.x), yy1 = fmaxf(bi.y, bj.y);
                float xx2 = fminf(bi.z, bj.z), yy2 = fminf(bi.w, bj.w);
                float inter = fmaxf(0.f, xx2 - xx1) * fmaxf(0.f, yy2 - yy1);
                float denom = ai + aj - inter;
                float t2 = inter + inter;
                if (t2 > denom * 1.00002f)      sup = true;
                else if (t2 < denom * 0.99998f) sup = false;
                else                            sup = (inter / denom > 0.5f);
            }
            uint32_t m = __ballot_sync(FULLM, sup);
            if ((tid & 31) == 0) smat[i * NW + w] = m;
        }
    }
    __syncthreads();

    // ---- greedy scan with row prefetch (exact reference semantics) ----
    if (tid == 0) {
        uint32_t rm[NW], row[NW], nxt[NW];
        #pragma unroll
        for (int w = 0; w < NW; w++) { rm[w] = 0u; row[w] = smat[w]; }
        for (int i = 0; i < nTop; i++) {
            if (i + 1 < nTop) {
                #pragma unroll
                for (int w = 0; w < NW; w++) nxt[w] = smat[(i + 1) * NW + w];
            }
            if (!((rm[i >> 5] >> (i & 31)) & 1u)) {
                #pragma unroll
                for (int w = 0; w < NW; w++) rm[w] |= row[w];
            }
            #pragma unroll
            for (int w = 0; w < NW; w++) row[w] = nxt[w];
        }
        #pragma unroll
        for (int w = 0; w < NW; w++) skeepw[w] = ~rm[w];
    }
    __syncthreads();

    // ---- output (B, C, TOPK, 6) ----
    if (tid < TOPK) {
        bool kp = (tid < nTop) && ((skeepw[tid >> 5] >> (tid & 31)) & 1u);
        size_t o = ((size_t)bc * TOPK + tid) * 6;
        float4 bx = sbox[tid];
        out[o + 0] = kp ? bx.x : 0.f;
        out[o + 1] = kp ? bx.y : 0.f;
        out[o + 2] = kp ? bx.z : 0.f;
        out[o + 3] = kp ? bx.w : 0.f;
        out[o + 4] = kp ? ssc[tid] : 0.f;
        out[o + 5] = kp ? (float)c : 0.f;
    }
}

// ---------------------------------------------------------------------------
extern "C" void kernel_launch(void* const* d_in, const int* in_sizes, int n_in,
                              void* d_out, int out_size) {
    const float* boxes  = (const float*)d_in[0];   // (8, 3, 5776, 4)
    const float* scores = (const float*)d_in[1];   // (8, 3, 5776, 80)
    float* out = (float*)d_out;                    // (8, 80, 200, 6)

    dim3 g1(NN / 48, NB);
    transpose_k<<<g1, 256>>>(scores);
    select_k<<<NBC, 256>>>(boxes);
    nmsfin_k<<<NBC, 256>>>(out);
}

// round 7
// speedup vs baseline: 1.7149x; 1.0824x over previous
#include <cuda_runtime.h>
#include <stdint.h>

#define NB 8
#define NC 80
#define NN 17328             /* 3*5776 */
#define NBC (NB * NC)        /* 640 */
#define TOPK 200
#define CAP 1024
#define NBINS 4096
#define NW 7                 /* ceil(200/32) */
#define HI_BITS 0x3F7AE000u  /* v >= 0.9799805f */
#define FULLM 0xFFFFFFFFu

// 44.3 MB scratch for transposed scores [B][C][N]
__device__ float g_scoresT[(size_t)NB * NC * NN];

// ---------------------------------------------------------------------------
// Kernel 1: transpose scores (B, N, C) -> (B, C, N).
// Read side: float4 coalesced LDG + STS.128 (conflict-free).
// Write side: lanes step r (LDS stride 81 % 32 = 17 -> conflict-free),
// coalesced scalar STG.
// ---------------------------------------------------------------------------
__global__ __launch_bounds__(256) void transpose_k(const float* __restrict__ scores) {
    __shared__ float tile[48 * 81];
    const int b  = blockIdx.y;
    const int n0 = blockIdx.x * 48;
    const float4* src4 = reinterpret_cast<const float4*>(
        scores + ((size_t)b * NN + n0) * NC);

    for (int f = threadIdx.x; f < 48 * 20; f += 256) {
        float4 v = src4[f];
        int r = f / 20, c4 = f % 20;
        float* p = &tile[r * 81 + c4 * 4];
        p[0] = v.x; p[1] = v.y; p[2] = v.z; p[3] = v.w;
    }
    __syncthreads();

    float* dstB = &g_scoresT[(size_t)b * NC * NN + n0];
    for (int j = threadIdx.x; j < NC * 48; j += 256) {
        int c = j / 48, r = j % 48;                 // lanes: consecutive r
        dstB[(size_t)c * NN + r] = tile[r * 81 + c];
    }
}

// ---------------------------------------------------------------------------
// Kernel 2 (fused): one CTA per (b,c). Streaming stash -> bitonic sort ->
// triangular ballot suppression matrix -> greedy scan -> output.
// ---------------------------------------------------------------------------
__device__ __forceinline__ uint32_t score_bin(uint32_t bits) {
    return (bits >= 0x3F800000u) ? (NBINS - 1) : ((bits - 0x3F000000u) >> 11);
}

struct NmsSmem {
    float4 sbox[TOPK];
    float  sar[TOPK];
    float  ssc[TOPK];
    uint32_t smat[TOPK * NW];
    uint32_t skeepw[NW];
};

__global__ __launch_bounds__(256) void nms_k(const float* __restrict__ boxes,
                                             float* __restrict__ out) {
    const int bc  = blockIdx.x;
    const int b   = bc / NC;
    const int c   = bc % NC;
    const int tid = threadIdx.x;
    const int lane = tid & 31;
    const float* base = g_scoresT + (size_t)bc * NN;

    __shared__ unsigned long long cand[CAP];         // 8 KB
    __shared__ union U {
        uint32_t hist[NBINS];                        // 16 KB, fallback only
        NmsSmem  m;                                  // 10.4 KB
        __device__ U() {}
    } u;
    __shared__ uint32_t part[256];
    __shared__ uint32_t candCnt;
    __shared__ int cutBin;

    if (tid == 0) candCnt = 0u;
    __syncthreads();

    // ---- streaming scan: per-thread stash, one shared atomic per warp ----
    unsigned long long mykeys[16];
    int h = 0;
    const float4* base4 = reinterpret_cast<const float4*>(base);
    for (int k = tid; k < NN / 4; k += 256) {
        float4 v4 = base4[k];
        uint32_t bb[4] = {__float_as_uint(v4.x), __float_as_uint(v4.y),
                          __float_as_uint(v4.z), __float_as_uint(v4.w)};
        #pragma unroll
        for (int uu = 0; uu < 4; uu++) {
            if (bb[uu] >= HI_BITS) {
                uint32_t n = (uint32_t)(4 * k + uu);
                if (h < 16)
                    mykeys[h] = ((unsigned long long)bb[uu] << 32) | (~n);
                h++;
            }
        }
    }

    int inc = h;
    #pragma unroll
    for (int o = 1; o < 32; o <<= 1) {
        int v = __shfl_up_sync(FULLM, inc, o);
        if (lane >= o) inc += v;
    }
    int exc = inc - h;
    int tot = __shfl_sync(FULLM, inc, 31);
    uint32_t wbase = 0;
    if (lane == 0) wbase = atomicAdd(&candCnt, (uint32_t)tot);
    wbase = __shfl_sync(FULLM, wbase, 0);
    int hw = (h < 16) ? h : 16;
    for (int t = 0; t < hw; t++) {
        uint32_t p = wbase + (uint32_t)exc + (uint32_t)t;
        if (p < CAP) cand[p] = mykeys[t];
    }
    __syncthreads();

    uint32_t cnt = candCnt;
    bool fast = (cnt >= TOPK) && (cnt <= CAP) && (h <= 16);
    fast = __syncthreads_and(fast);
    int cc;

    if (fast) {
        cc = (int)cnt;
    } else {
        // ---- exactness fallback (cold): histogram cut + rescan ----
        for (int i = tid; i < NBINS; i += 256) u.hist[i] = 0u;
        if (tid == 0) candCnt = 0u;
        __syncthreads();
        for (int i = tid; i < NN; i += 256) {
            float v = base[i];
            if (v > 0.5f) atomicAdd(&u.hist[score_bin(__float_as_uint(v))], 1u);
        }
        __syncthreads();
        uint32_t ps = 0;
        #pragma unroll
        for (int k = 0; k < 16; k++) ps += u.hist[tid * 16 + k];
        part[tid] = ps;
        __syncthreads();
        if (tid == 0) {
            uint32_t suf = 0; int g = -1; uint32_t sufG = 0;
            for (int t = 255; t >= 0; t--) {
                uint32_t ns = suf + part[t];
                if (ns >= TOPK) { g = t; sufG = suf; break; }
                suf = ns;
            }
            int hstar = 0;
            if (g >= 0) {
                uint32_t run = sufG;
                for (int bn = g * 16 + 15; bn >= g * 16; bn--) {
                    run += u.hist[bn];
                    if (run >= TOPK) { hstar = bn; break; }
                }
            }
            cutBin = hstar;
        }
        __syncthreads();
        const int hstar = cutBin;
        for (int i = tid; i < NN; i += 256) {
            float v = base[i];
            if (v > 0.5f) {
                uint32_t bits = __float_as_uint(v);
                if (score_bin(bits) >= (uint32_t)hstar) {
                    uint32_t p = atomicAdd(&candCnt, 1u);
                    if (p < CAP)
                        cand[p] = ((unsigned long long)bits << 32) | (~(uint32_t)i);
                }
            }
        }
        __syncthreads();
        cc = (candCnt < (uint32_t)CAP) ? (int)candCnt : CAP;
    }

    // ---- pad + bitonic sort (descending) ----
    const int M = (cc <= 256) ? 256 : (cc <= 512 ? 512 : CAP);
    for (int i = tid; i < M; i += 256)
        if (i >= cc) cand[i] = 0ULL;
    __syncthreads();

    for (int k = 2; k <= M; k <<= 1) {
        for (int j = k >> 1; j > 0; j >>= 1) {
            for (int p = tid; p < (M >> 1); p += 256) {
                int i   = ((p & ~(j - 1)) << 1) | (p & (j - 1));
                int ixj = i | j;
                unsigned long long a = cand[i], bb = cand[ixj];
                bool desc = ((i & k) == 0);
                if (desc ? (a < bb) : (a > bb)) { cand[i] = bb; cand[ixj] = a; }
            }
            __syncthreads();
        }
    }

    const int nTop = (cc < TOPK) ? cc : TOPK;

    // ---- winners -> smem tables; zero smat ----
    if (tid < TOPK) {
        float4 bx = make_float4(0.f, 0.f, 0.f, 0.f);
        float sc = 0.f, ar = 0.f;
        if (tid < nTop) {
            unsigned long long key = cand[tid];
            uint32_t idx  = ~(uint32_t)(key & 0xFFFFFFFFull);
            uint32_t bits = (uint32_t)(key >> 32);
            bx = reinterpret_cast<const float4*>(boxes)[(size_t)b * NN + idx];
            sc = __uint_as_float(bits);
            ar = (bx.z - bx.x) * (bx.w - bx.y);
        }
        u.m.sbox[tid] = bx;
        u.m.sar[tid]  = ar;
        u.m.ssc[tid]  = sc;
    }
    for (int i = tid; i < TOPK * NW; i += 256) u.m.smat[i] = 0u;
    __syncthreads();

    // ---- triangular ballot suppression matrix ----
    if (tid < NW * 32) {
        const int w = tid >> 5;
        const int j = tid;                     // column
        float4 bj = make_float4(0.f, 0.f, 0.f, 0.f);
        float  aj = 0.f;
        bool valid = (j < nTop);
        if (valid) { bj = u.m.sbox[j]; aj = u.m.sar[j]; }
        const int iMax = (nTop < 32 * w + 31) ? nTop : (32 * w + 31);
        #pragma unroll 2
        for (int i = 0; i < iMax; i++) {
            float4 bi = u.m.sbox[i];
            float  ai = u.m.sar[i];
            bool sup = false;
            if (valid && j > i) {
                float xx1 = fmaxf(bi.x, bj.x), yy1 = fmaxf(bi.y, bj.y);
                float xx2 = fminf(bi.z, bj.z), yy2 = fminf(bi.w, bj.w);
                float inter = fmaxf(0.f, xx2 - xx1) * fmaxf(0.f, yy2 - yy1);
                float denom = ai + aj - inter;
                float t2 = inter + inter;
                if (t2 > denom * 1.00002f)      sup = true;
                else if (t2 < denom * 0.99998f) sup = false;
                else                            sup = (inter / denom > 0.5f);
            }
            uint32_t m = __ballot_sync(FULLM, sup);
            if (lane == 0) u.m.smat[i * NW + w] = m;
        }
    }
    __syncthreads();

    // ---- greedy scan with row prefetch (exact reference semantics) ----
    if (tid == 0) {
        uint32_t rm[NW], row[NW], nxt[NW];
        #pragma unroll
        for (int w = 0; w < NW; w++) { rm[w] = 0u; row[w] = u.m.smat[w]; }
        for (int i = 0; i < nTop; i++) {
            if (i + 1 < nTop) {
                #pragma unroll
                for (int w = 0; w < NW; w++) nxt[w] = u.m.smat[(i + 1) * NW + w];
            }
            if (!((rm[i >> 5] >> (i & 31)) & 1u)) {
                #pragma unroll
                for (int w = 0; w < NW; w++) rm[w] |= row[w];
            }
            #pragma unroll
            for (int w = 0; w < NW; w++) row[w] = nxt[w];
        }
        #pragma unroll
        for (int w = 0; w < NW; w++) u.m.skeepw[w] = ~rm[w];
    }
    __syncthreads();

    // ---- output (B, C, TOPK, 6) ----
    if (tid < TOPK) {
        bool kp = (tid < nTop) && ((u.m.skeepw[tid >> 5] >> (tid & 31)) & 1u);
        size_t o = ((size_t)bc * TOPK + tid) * 6;
        float4 bx = u.m.sbox[tid];
        out[o + 0] = kp ? bx.x : 0.f;
        out[o + 1] = kp ? bx.y : 0.f;
        out[o + 2] = kp ? bx.z : 0.f;
        out[o + 3] = kp ? bx.w : 0.f;
        out[o + 4] = kp ? u.m.ssc[tid] : 0.f;
        out[o + 5] = kp ? (float)c : 0.f;
    }
}

// ---------------------------------------------------------------------------
extern "C" void kernel_launch(void* const* d_in, const int* in_sizes, int n_in,
                              void* d_out, int out_size) {
    const float* boxes  = (const float*)d_in[0];   // (8, 3, 5776, 4)
    const float* scores = (const float*)d_in[1];   // (8, 3, 5776, 80)
    float* out = (float*)d_out;                    // (8, 80, 200, 6)

    dim3 g1(NN / 48, NB);
    transpose_k<<<g1, 256>>>(scores);
    nms_k<<<NBC, 256>>>(boxes, out);
}